// round 10
// baseline (speedup 1.0000x reference)
#include <cuda_runtime.h>

#define NN   20000
#define NE   160000
#define INF  16
#define H1   512
#define H2   1024
#define OUTF 16

#define GRID 296                 // 2 blocks per SM, all resident
#define BLK  512
#define NT   (GRID * BLK)        // 151552 threads
#define WPB  (BLK / 32)          // 16 warps/block
#define NW   (GRID * WPB)        // 4736 warps

#define NG    625                // node groups of 32 (625*32 = 20000)
#define NSL   16                 // j-slices (512/16 = 32 j per slice)
#define ITEMS (NG * NSL)         // 10000 MLP work items

typedef unsigned long long ull;

// Scratch (device globals; zero-initialized at module load)
__device__ __align__(128) float  g_deg[NN];      // zeroed at load; re-zeroed in S2
__device__ __align__(128) float  g_dinv[NN];
__device__ __align__(128) float4 g_xs[NN * 4];   // dinv[i] * x[i]
__device__ __align__(128) float4 g_y1[NN * 4];   // xs[self] + sum_in xs[s]
__device__ __align__(128) float4 g_tr[NN * 4];   // raw t (RED accumulator; zeroed in S0)
__device__ __align__(128) float4 g_ts[NN * 4];   // dinv * t
__device__ __align__(128) float  g_wf[H1 * OUTF]; // W2@Wl row-major [512][16]
__device__ __align__(128) float  g_cvec[32];     // b2@Wl + bl

// Grid barrier: monotone counters, never reset -> graph-replay safe
__device__ unsigned g_arrive[8];
__device__ unsigned g_release[8];

__device__ __forceinline__ void grid_sync(int b) {
    __syncthreads();
    if (threadIdx.x == 0) {
        __threadfence();
        unsigned old = atomicAdd(&g_arrive[b], 1u);
        unsigned target = old / (unsigned)GRID + 1u;
        if (old % (unsigned)GRID == (unsigned)(GRID - 1))
            atomicAdd(&g_release[b], 1u);
        while (*(volatile unsigned*)&g_release[b] < target) {}
        __threadfence();
    }
    __syncthreads();
}

// ---- f32x2 helpers ----
__device__ __forceinline__ ull pack2(float a) {
    ull r; asm("mov.b64 %0, {%1, %1};" : "=l"(r) : "f"(a)); return r;
}
__device__ __forceinline__ ull fma2(ull a, ull b, ull c) {
    ull d; asm("fma.rn.f32x2 %0, %1, %2, %3;" : "=l"(d) : "l"(a), "l"(b), "l"(c));
    return d;
}
__device__ __forceinline__ float2 unpack2(ull v) {
    float2 f; asm("mov.b64 {%0, %1}, %2;" : "=f"(f.x), "=f"(f.y) : "l"(v));
    return f;
}
__device__ __forceinline__ void redv4(float* p, float4 v) {
    asm volatile("red.global.add.v4.f32 [%0], {%1,%2,%3,%4};"
                 :: "l"(p), "f"(v.x), "f"(v.y), "f"(v.z), "f"(v.w) : "memory");
}

extern "C" __global__ void __launch_bounds__(BLK, 2)
gcn_persistent(const float* __restrict__ x,  const int* __restrict__ g,
               const float* __restrict__ W1, const float* __restrict__ b1,
               const float* __restrict__ W2, const float* __restrict__ b2,
               const float* __restrict__ Wl, const float* __restrict__ bl,
               float* __restrict__ out)
{
    extern __shared__ ull smem_u[];
    ull* sW1 = smem_u;          // [256 jp][16 k]: (W1[k][2jp], W1[k][2jp+1])  32 KB
    ull* sWf = smem_u + 4096;   // [512 j][8 cp]: (Wf[j][2cp], Wf[j][2cp+1])   32 KB

    const int tid  = threadIdx.x;
    const int gid  = blockIdx.x * BLK + tid;
    const int wid  = tid >> 5, lane = tid & 31;
    const int gw   = blockIdx.x * WPB + wid;

    // ========== S0: stage W1T; zero g_tr; deg REDs; Wf=W2@Wl; cvec =========
    // sW1[jp*16+k] = ull at W1[k][2jp] (W1 row-major [16][512])
    for (int idx = tid; idx < 4096; idx += BLK) {
        int jp = idx >> 4, k = idx & 15;
        sW1[idx] = __ldg((const ull*)W1 + k * 256 + jp);
    }

    {   // zero the raw-t RED accumulator
        const float4 z = make_float4(0.f, 0.f, 0.f, 0.f);
        for (int i = gid; i < NN * 4; i += NT) g_tr[i] = z;
    }

    if (gw < H1) {  // fused weight: one warp per j-row; store row-major [j][16]
        const int j = gw;
        float acc[16];
#pragma unroll
        for (int c = 0; c < 16; c++) acc[c] = 0.0f;
        const float* w2r = W2 + (size_t)j * H2;
#pragma unroll 4
        for (int jj = 0; jj < H2 / 32; jj++) {
            int m = jj * 32 + lane;
            float w2 = __ldg(w2r + m);
            const float4* wl = (const float4*)(Wl + (size_t)m * OUTF);
            float4 a = __ldg(wl), b = __ldg(wl + 1), c4 = __ldg(wl + 2), d4 = __ldg(wl + 3);
            acc[0]  += w2 * a.x;  acc[1]  += w2 * a.y;  acc[2]  += w2 * a.z;  acc[3]  += w2 * a.w;
            acc[4]  += w2 * b.x;  acc[5]  += w2 * b.y;  acc[6]  += w2 * b.z;  acc[7]  += w2 * b.w;
            acc[8]  += w2 * c4.x; acc[9]  += w2 * c4.y; acc[10] += w2 * c4.z; acc[11] += w2 * c4.w;
            acc[12] += w2 * d4.x; acc[13] += w2 * d4.y; acc[14] += w2 * d4.z; acc[15] += w2 * d4.w;
        }
#pragma unroll
        for (int off = 16; off; off >>= 1)
#pragma unroll
            for (int c = 0; c < 16; c++) acc[c] += __shfl_xor_sync(0xFFFFFFFFu, acc[c], off);
        if (lane < 16) g_wf[j * 16 + lane] = acc[lane];
    } else if (gw == NW - 1) {
        int c = lane & 15, half = lane >> 4;
        float s = 0.0f;
        for (int j = half * (H2 / 2); j < (half + 1) * (H2 / 2); j++)
            s += __ldg(b2 + j) * __ldg(Wl + (size_t)j * OUTF + c);
        s += __shfl_xor_sync(0xFFFFFFFFu, s, 16);
        if (lane < 16) g_cvec[c] = s + __ldg(bl + c);
    }

    // degree atomics overlap with fusew (deg zero at entry)
    for (int e = gid; e < NE; e += NT)
        atomicAdd(&g_deg[g[NE + e]], 1.0f);
    grid_sync(0);

    // stage Wf into smem (row-major copy; stable after sync0)
    for (int i = tid; i < 4096; i += BLK)
        sWf[i] = __ldcg((const ull*)g_wf + i);

    // ========== S2: dinv = rsqrt(deg+1); xs = dinv*x; y1 = xs; deg := 0 ====
    for (int i = gid; i < NN; i += NT) {
        float dv = rsqrtf(__ldcg(&g_deg[i]) + 1.0f);   // +1 = self-loop
        __stcg(&g_deg[i], 0.0f);                       // reset for next replay
        g_dinv[i] = dv;
        const float4* xr = (const float4*)(x + (size_t)i * INF);
#pragma unroll
        for (int q = 0; q < 4; q++) {
            float4 v = __ldg(xr + q);
            float4 s = make_float4(dv * v.x, dv * v.y, dv * v.z, dv * v.w);
            g_xs[i * 4 + q] = s;
            g_y1[i * 4 + q] = s;
        }
    }
    grid_sync(1);

    // ========== S3: y1[d] += xs[s]  (vector REDs) =========================
    for (int e = gid; e < NE; e += NT) {
        int s = g[e], d = g[NE + e];
        const float4* xr = &g_xs[s * 4];
        float* o = (float*)&g_y1[d * 4];
#pragma unroll
        for (int q = 0; q < 4; q++) redv4(o + q * 4, __ldcg(xr + q));
    }
    grid_sync(2);

    // ========== S4: MLP, lane = node, broadcast weights, f32x2 ============
    // item = (group g of 32 nodes, j-slice s of 32 hidden units)
    for (int item = gw; item < ITEMS; item += NW) {
        const int grp = item % NG;
        const int sl  = item / NG;
        const int node = grp * 32 + lane;

        float dv = __ldcg(&g_dinv[node]);
        const float4* yr = &g_y1[node * 4];
        float4 a0 = __ldcg(yr), a1 = __ldcg(yr + 1), a2 = __ldcg(yr + 2), a3 = __ldcg(yr + 3);
        float ya[16] = {dv*a0.x, dv*a0.y, dv*a0.z, dv*a0.w,
                        dv*a1.x, dv*a1.y, dv*a1.z, dv*a1.w,
                        dv*a2.x, dv*a2.y, dv*a2.z, dv*a2.w,
                        dv*a3.x, dv*a3.y, dv*a3.z, dv*a3.w};

        ull acc2[8];
#pragma unroll
        for (int cp = 0; cp < 8; cp++) acc2[cp] = 0ull;

#pragma unroll
        for (int u = 0; u < 16; u++) {
            const int jp = sl * 16 + u;          // j-pair (2jp, 2jp+1)
            // ---- stage 1: h for j-pair, f32x2 over the pair ----
            ull h2 = __ldg((const ull*)b1 + jp); // (b1[j0], b1[j1])
            const ulonglong2* w1v = (const ulonglong2*)(sW1 + jp * 16);
#pragma unroll
            for (int kk = 0; kk < 8; kk++) {
                ulonglong2 w = w1v[kk];          // k=2kk, 2kk+1 (broadcast LDS)
                h2 = fma2(pack2(ya[2 * kk]),     w.x, h2);
                h2 = fma2(pack2(ya[2 * kk + 1]), w.y, h2);
            }
            float2 hf = unpack2(h2);
            ull hp0 = pack2(fmaxf(hf.x, 0.0f));  // relu(h[j0])
            ull hp1 = pack2(fmaxf(hf.y, 0.0f));  // relu(h[j1])

            // ---- stage 2: acc over c, f32x2 over c-pairs ----
            const ulonglong2* wf0 = (const ulonglong2*)(sWf + (2 * jp) * 8);
            const ulonglong2* wf1 = (const ulonglong2*)(sWf + (2 * jp + 1) * 8);
#pragma unroll
            for (int cq = 0; cq < 4; cq++) {
                ulonglong2 wa = wf0[cq];         // broadcast LDS
                ulonglong2 wb = wf1[cq];
                acc2[2 * cq]     = fma2(hp0, wa.x, acc2[2 * cq]);
                acc2[2 * cq + 1] = fma2(hp0, wa.y, acc2[2 * cq + 1]);
                acc2[2 * cq]     = fma2(hp1, wb.x, acc2[2 * cq]);
                acc2[2 * cq + 1] = fma2(hp1, wb.y, acc2[2 * cq + 1]);
            }
        }

        // epilogue: RED raw partial t into g_tr[node]
        float* o = (float*)&g_tr[node * 4];
#pragma unroll
        for (int q = 0; q < 4; q++) {
            float2 u0 = unpack2(acc2[2 * q]);
            float2 u1 = unpack2(acc2[2 * q + 1]);
            redv4(o + q * 4, make_float4(u0.x, u0.y, u1.x, u1.y));
        }
    }
    grid_sync(3);

    // ========== S5: ts = dinv*t; out init = dinv*ts + cvec ================
    for (int i = gid; i < NN; i += NT) {
        float dv = __ldcg(&g_dinv[i]);
        const float4* cv = (const float4*)g_cvec;
#pragma unroll
        for (int q = 0; q < 4; q++) {
            float4 t = __ldcg(&g_tr[i * 4 + q]);
            float4 ts = make_float4(dv * t.x, dv * t.y, dv * t.z, dv * t.w);
            g_ts[i * 4 + q] = ts;
            float4 c = cv[q];
            ((float4*)out)[i * 4 + q] = make_float4(dv * ts.x + c.x, dv * ts.y + c.y,
                                                    dv * ts.z + c.z, dv * ts.w + c.w);
        }
    }
    grid_sync(4);

    // ========== S6: out[d] += dinv[d] * ts[s]  (vector REDs) ==============
    for (int e = gid; e < NE; e += NT) {
        int s = g[e], d = g[NE + e];
        float dvd = __ldcg(&g_dinv[d]);
        const float4* tr = &g_ts[s * 4];
        float* o = out + (size_t)d * OUTF;
#pragma unroll
        for (int q = 0; q < 4; q++) {
            float4 v = __ldcg(tr + q);
            redv4(o + q * 4, make_float4(dvd * v.x, dvd * v.y, dvd * v.z, dvd * v.w));
        }
    }
}

// ---------------------------------------------------------------- launch
extern "C" void kernel_launch(void* const* d_in, const int* in_sizes, int n_in,
                              void* d_out, int out_size) {
    const float* x  = (const float*)d_in[0];
    const int*   g  = (const int*)d_in[1];
    const float* W1 = (const float*)d_in[2];
    const float* b1 = (const float*)d_in[3];
    const float* W2 = (const float*)d_in[4];
    const float* b2 = (const float*)d_in[5];
    const float* Wl = (const float*)d_in[6];
    const float* bl = (const float*)d_in[7];
    float* out = (float*)d_out;

    cudaFuncSetAttribute(gcn_persistent,
                         cudaFuncAttributeMaxDynamicSharedMemorySize, 65536);
    gcn_persistent<<<GRID, BLK, 65536>>>(x, g, W1, b1, W2, b2, Wl, bl, out);
}